// round 14
// baseline (speedup 1.0000x reference)
#include <cuda_runtime.h>
#include <cuda_fp16.h>
#include <cstdint>
#include <cstddef>

#define B_      256
#define IMG_    256
#define G_      64
#define HID_    512
#define NSTEP_  16
#define GATES_  (4*HID_)     // 2048
#define XDIM_   (G_*G_)      // 4096
#define KTOT_   (XDIM_+HID_) // 4608
#define PI_     3.14159265358979f

// ---------------- scratch (static device globals; no allocation) -------------
__device__ float g_H[B_*HID_];
__device__ float g_C[B_*HID_];
__device__ float g_GP[B_*3];
__device__ float g_gates[B_*GATES_];
// split operands for the tensor-core gates GEMM
__device__ __half g_Ahi[B_*KTOT_];      // rows b, cols [X | H]
__device__ __half g_Alo[B_*KTOT_];
__device__ __half g_Whi[GATES_*KTOT_];  // rows n, cols [Wih | Whh]
__device__ __half g_Wlo[GATES_*KTOT_];
// split images (loop-invariant; split once per launch)
__device__ __half g_Ihi[B_*2*IMG_*IMG_];
__device__ __half g_Ilo[B_*2*IMG_*IMG_];

#define LO_SCALE 2048.0f
#define LO_INV   4.8828125e-4f

__device__ __forceinline__ void split2(float v, __half& hi, __half& lo) {
    hi = __float2half_rn(v);
    lo = __float2half_rn((v - __half2float(hi)) * LO_SCALE);
}

__device__ __forceinline__ void cp16(uint32_t dst, const void* src) {
    asm volatile("cp.async.cg.shared.global [%0], [%1], 16;" :: "r"(dst), "l"(src));
}
__device__ __forceinline__ void ldsm4(uint32_t addr, uint32_t& r0, uint32_t& r1,
                                      uint32_t& r2, uint32_t& r3) {
    asm volatile("ldmatrix.sync.aligned.m8n8.x4.shared.b16 {%0,%1,%2,%3}, [%4];"
                 : "=r"(r0), "=r"(r1), "=r"(r2), "=r"(r3) : "r"(addr));
}
__device__ __forceinline__ void mma16816(float* c, uint32_t a0, uint32_t a1,
                                         uint32_t a2, uint32_t a3,
                                         uint32_t b0, uint32_t b1) {
    asm volatile("mma.sync.aligned.m16n8k16.row.col.f32.f16.f16.f32 "
                 "{%0,%1,%2,%3}, {%4,%5,%6,%7}, {%8,%9}, {%0,%1,%2,%3};"
                 : "+f"(c[0]), "+f"(c[1]), "+f"(c[2]), "+f"(c[3])
                 : "r"(a0), "r"(a1), "r"(a2), "r"(a3), "r"(b0), "r"(b1));
}

// ---------------- init: zero H, C, A; seed GP for step 0 (H=0) ---------------
__global__ void init_kernel(const float* __restrict__ bg) {
    int i = blockIdx.x * blockDim.x + threadIdx.x;
    if (i < B_*HID_) { g_H[i] = 0.f; g_C[i] = 0.f; }
    if (i < B_*KTOT_) {
        g_Ahi[i] = __float2half(0.f);
        g_Alo[i] = __float2half(0.f);
    }
    if (i < B_*3) g_GP[i] = tanhf(bg[i % 3]);
}

// ---------------- pre-split W (once per launch) -------------------------------
__global__ void presplit_kernel(const float* __restrict__ Wih,
                                const float* __restrict__ Whh) {
    int n = blockIdx.x;
    for (int k = threadIdx.x; k < KTOT_; k += 256) {
        float w = (k < XDIM_) ? Wih[(size_t)n*XDIM_ + k]
                              : Whh[(size_t)n*HID_ + k - XDIM_];
        __half hi, lo; split2(w, hi, lo);
        g_Whi[(size_t)n*KTOT_ + k] = hi;
        g_Wlo[(size_t)n*KTOT_ + k] = lo;
    }
}

// ---------------- pre-split images (once per launch) --------------------------
__global__ void presplit_img_kernel(const float* __restrict__ imgs) {
    size_t base = (size_t)blockIdx.x * (IMG_*IMG_);
    for (int k = threadIdx.x; k < IMG_*IMG_; k += 256) {
        float v = imgs[base + k];
        __half hi, lo; split2(v, hi, lo);
        g_Ihi[base + k] = hi;
        g_Ilo[base + k] = lo;
    }
}

// ---------------- tensor-core glimpse: filterbank + 2 HMMA GEMMs -------------
#define SM_FW_HI  0
#define SM_FW_LO  33792
#define SM_IMG    67584
#define SM_T_HI   67584
#define SM_T_LO   101376
#define SM_RED    149504
#define SM_RW     151552
#define SM_RH     151808
#define SM_TOTAL  152064

extern __shared__ char gl_smem[];
__global__ __launch_bounds__(512, 1) void glimpse_kernel(int ch) {
    uint32_t sb = (uint32_t)__cvta_generic_to_shared(gl_smem);
    float* s_red = (float*)(gl_smem + SM_RED);
    float* s_rw  = (float*)(gl_smem + SM_RW);
    float* s_rh  = (float*)(gl_smem + SM_RH);

    int b = blockIdx.x;
    int t = threadIdx.x;
    int l = t & 31, wid = t >> 5;
    int rA = (l & 7) + 8*((l >> 3) & 1);
    int cA = l >> 4;
    int rB = (l & 7) + 8*(l >> 4);
    int cB = (l >> 3) & 1;
    int g  = l >> 2, tig = l & 3;

    size_t ibase = ((size_t)b*2 + ch) * (IMG_*IMG_);

    auto issue = [&](int cc) {
        int st = cc & 1;
        #pragma unroll
        for (int j = 0; j < 2; j++) {
            int uid = t + 512*j;
            int row = uid >> 2, u = uid & 3;
            size_t goff = ibase + (size_t)row*IMG_ + cc*32 + u*8;
            uint32_t doff = sb + SM_IMG + st*40960 + row*80 + u*16;
            cp16(doff, g_Ihi + goff);
            cp16(doff + 20480, g_Ilo + goff);
        }
    };
    issue(0); asm volatile("cp.async.commit_group;" ::: "memory");
    issue(1); asm volatile("cp.async.commit_group;" ::: "memory");

    float d   = g_GP[b*3 + 2];
    float ch0 = g_GP[b*3 + 0];
    float cw  = g_GP[b*3 + 1];
    float ad      = fabsf(d);
    float delta   = 4.f * (1.f - ad);
    float gamma   = expf(1.f - 2.f*ad);
    float inv_g   = 1.f / gamma;
    float eps_adj = 1e-4f * PI_ * gamma;
    float center_h = 127.5f * (ch0 + 1.f);
    float center_w = 127.5f * (cw  + 1.f);

    {
        int j = t & 63, wg = t >> 6;
        float mu = center_w + delta * ((float)j - 31.5f);
        __half* fh = (__half*)(gl_smem + SM_FW_HI) + j*264;
        __half* fl = (__half*)(gl_smem + SM_FW_LO) + j*264;
        float s = 0.f;
        #pragma unroll 8
        for (int w = wg*32; w < wg*32 + 32; w++) {
            float u = ((float)w - mu) * inv_g;
            float v = 1.f / (1.f + u*u);
            s += v;
            __half hi, lo; split2(v, hi, lo);
            fh[w] = hi; fl[w] = lo;
        }
        s_red[t] = s;
    }
    __syncthreads();
    if (t < 64) {
        float s = 0.f;
        #pragma unroll
        for (int p = 0; p < 8; p++) s += s_red[t + 64*p];
        s_rw[t] = 1.f / (s + eps_adj);
    }

    int mt = wid;
    float chh[8][4], cmid[8][4];
    #pragma unroll
    for (int f = 0; f < 8; f++)
        #pragma unroll
        for (int q = 0; q < 4; q++) { chh[f][q] = 0.f; cmid[f][q] = 0.f; }

    for (int c = 0; c < 8; c++) {
        asm volatile("cp.async.wait_group 1;" ::: "memory");
        __syncthreads();
        uint32_t ahB = sb + SM_IMG + (c & 1)*40960 + (mt*16 + rA)*80 + cA*16;
        uint32_t alB = ahB + 20480;
        #pragma unroll
        for (int ks = 0; ks < 2; ks++) {
            uint32_t kb = ks*32;
            uint32_t aH0,aH1,aH2,aH3, aL0,aL1,aL2,aL3;
            ldsm4(ahB + kb, aH0, aH1, aH2, aH3);
            ldsm4(alB + kb, aL0, aL1, aL2, aL3);
            #pragma unroll
            for (int p = 0; p < 4; p++) {
                uint32_t bh = sb + SM_FW_HI + (uint32_t)((p*16 + rB)*528) + c*64 + cB*16 + kb;
                uint32_t bH0,bH1,bH2,bH3, bL0,bL1,bL2,bL3;
                ldsm4(bh, bH0, bH1, bH2, bH3);
                ldsm4(bh + 33792, bL0, bL1, bL2, bL3);
                int f0 = 2*p, f1 = 2*p + 1;
                mma16816(chh[f0],  aH0,aH1,aH2,aH3, bH0,bH1);
                mma16816(chh[f1],  aH0,aH1,aH2,aH3, bH2,bH3);
                mma16816(cmid[f0], aL0,aL1,aL2,aL3, bH0,bH1);
                mma16816(cmid[f1], aL0,aL1,aL2,aL3, bH2,bH3);
                mma16816(cmid[f0], aH0,aH1,aH2,aH3, bL0,bL1);
                mma16816(cmid[f1], aH0,aH1,aH2,aH3, bL2,bL3);
            }
        }
        __syncthreads();
        if (c + 2 < 8) issue(c + 2);
        asm volatile("cp.async.commit_group;" ::: "memory");
    }
    __syncthreads();

    {
        __half* th = (__half*)(gl_smem + SM_T_HI);
        __half* tl = (__half*)(gl_smem + SM_T_LO);
        #pragma unroll
        for (int f = 0; f < 8; f++) {
            #pragma unroll
            for (int q = 0; q < 4; q++) {
                int j = f*8 + tig*2 + (q & 1);
                int r = mt*16 + g + 8*(q >> 1);
                float val = (chh[f][q] + cmid[f][q]*LO_INV) * s_rw[j];
                __half hi, lo; split2(val, hi, lo);
                th[j*264 + r] = hi;
                tl[j*264 + r] = lo;
            }
        }
    }

    {
        int i = t & 63, rg = t >> 6;
        float mu = center_h + delta * ((float)i - 31.5f);
        __half* fh = (__half*)(gl_smem + SM_FW_HI) + i*264;
        __half* fl = (__half*)(gl_smem + SM_FW_LO) + i*264;
        float s = 0.f;
        #pragma unroll 8
        for (int r = rg*32; r < rg*32 + 32; r++) {
            float u = ((float)r - mu) * inv_g;
            float v = 1.f / (1.f + u*u);
            s += v;
            __half hi, lo; split2(v, hi, lo);
            fh[r] = hi; fl[r] = lo;
        }
        s_red[t] = s;
    }
    __syncthreads();
    if (t < 64) {
        float s = 0.f;
        #pragma unroll
        for (int p = 0; p < 8; p++) s += s_red[t + 64*p];
        s_rh[t] = 1.f / (s + eps_adj);
    }
    __syncthreads();

    int mt2 = wid & 3, np = wid >> 2;
    float c2h[2][4], c2m[2][4];
    #pragma unroll
    for (int f = 0; f < 2; f++)
        #pragma unroll
        for (int q = 0; q < 4; q++) { c2h[f][q] = 0.f; c2m[f][q] = 0.f; }

    #pragma unroll 2
    for (int ks2 = 0; ks2 < 16; ks2++) {
        uint32_t kb = (uint32_t)ks2*32;
        uint32_t ah = sb + SM_FW_HI + (uint32_t)((mt2*16 + rA)*528) + kb + cA*16;
        uint32_t bh = sb + SM_T_HI  + (uint32_t)((np*16 + rB)*528) + kb + cB*16;
        uint32_t aH0,aH1,aH2,aH3, aL0,aL1,aL2,aL3;
        uint32_t bH0,bH1,bH2,bH3, bL0,bL1,bL2,bL3;
        ldsm4(ah, aH0, aH1, aH2, aH3);
        ldsm4(ah + 33792, aL0, aL1, aL2, aL3);
        ldsm4(bh, bH0, bH1, bH2, bH3);
        ldsm4(bh + 33792, bL0, bL1, bL2, bL3);
        mma16816(c2h[0], aH0,aH1,aH2,aH3, bH0,bH1);
        mma16816(c2h[1], aH0,aH1,aH2,aH3, bH2,bH3);
        mma16816(c2m[0], aL0,aL1,aL2,aL3, bH0,bH1);
        mma16816(c2m[1], aL0,aL1,aL2,aL3, bH2,bH3);
        mma16816(c2m[0], aH0,aH1,aH2,aH3, bL0,bL1);
        mma16816(c2m[1], aH0,aH1,aH2,aH3, bL2,bL3);
    }

    {
        __half* ahi = g_Ahi + (size_t)b * KTOT_;
        __half* alo = g_Alo + (size_t)b * KTOT_;
        #pragma unroll
        for (int f = 0; f < 2; f++) {
            #pragma unroll
            for (int q = 0; q < 4; q++) {
                int i = mt2*16 + g + 8*(q >> 1);
                int j = np*16 + f*8 + tig*2 + (q & 1);
                float val = (c2h[f][q] + c2m[f][q]*LO_INV) * s_rh[i];
                __half hi, lo; split2(val, hi, lo);
                ahi[i*64 + j] = hi;
                alo[i*64 + j] = lo;
            }
        }
    }
}

// ---------------- gates GEMM: 64m x 64n tile, 128 thr, 2-stage cp.async ------
#define AHOFF   0
#define ALOFF   5120
#define BHOFF   10240
#define BLOFF   15360
#define SSTAGE  20480
#define NKC     144     // 4608 / 32

__global__ __launch_bounds__(128) void gates_kernel(
        const float* __restrict__ bih, const float* __restrict__ bhh) {
    __shared__ __align__(128) unsigned char gsm[2*SSTAGE];
    uint32_t sb = (uint32_t)__cvta_generic_to_shared(gsm);

    int t = threadIdx.x;
    int l = t & 31, wm = t >> 5;                   // 4 warps: m-subtile
    int m0 = blockIdx.y * 64, n0 = blockIdx.x * 64;

    int rA = (l & 7) + 8*((l >> 3) & 1) + wm*16;
    int cA = l >> 4;
    uint32_t aoffH = AHOFF + rA*80 + cA*16;
    uint32_t aoffL = ALOFF + rA*80 + cA*16;
    int rB = (l & 7) + 8*(l >> 4);
    int cB = (l >> 3) & 1;
    uint32_t boffH = BHOFF + rB*80 + cB*16;
    uint32_t boffL = BLOFF + rB*80 + cB*16;

    float chh[8][4], cmid[8][4];
    #pragma unroll
    for (int f = 0; f < 8; f++)
        #pragma unroll
        for (int q = 0; q < 4; q++) { chh[f][q] = 0.f; cmid[f][q] = 0.f; }

    auto issue = [&](int kc, int st) {
        uint32_t base = sb + st*SSTAGE;
        int k0 = kc * 32;
        #pragma unroll
        for (int j = 0; j < 2; j++) {              // A: 256 16B units (64 rows)
            int uid = t + 128*j;
            int row = uid >> 2, u = uid & 3;
            size_t gidx = (size_t)(m0 + row)*KTOT_ + k0 + u*8;
            uint32_t doff = row*80 + u*16;
            cp16(base + AHOFF + doff, g_Ahi + gidx);
            cp16(base + ALOFF + doff, g_Alo + gidx);
        }
        #pragma unroll
        for (int j = 0; j < 2; j++) {              // B: 256 16B units (64 rows)
            int uid = t + 128*j;
            int row = uid >> 2, u = uid & 3;
            size_t gidx = (size_t)(n0 + row)*KTOT_ + k0 + u*8;
            uint32_t doff = row*80 + u*16;
            cp16(base + BHOFF + doff, g_Whi + gidx);
            cp16(base + BLOFF + doff, g_Wlo + gidx);
        }
    };

    issue(0, 0); asm volatile("cp.async.commit_group;" ::: "memory");
    issue(1, 1); asm volatile("cp.async.commit_group;" ::: "memory");

    for (int kc = 0; kc < NKC; kc++) {
        int st = kc & 1;
        asm volatile("cp.async.wait_group 1;" ::: "memory");
        __syncthreads();
        uint32_t base = sb + st*SSTAGE;
        #pragma unroll
        for (int ks = 0; ks < 2; ks++) {
            uint32_t kb = ks*32;
            uint32_t aH0,aH1,aH2,aH3, aL0,aL1,aL2,aL3;
            ldsm4(base + aoffH + kb, aH0, aH1, aH2, aH3);
            ldsm4(base + aoffL + kb, aL0, aL1, aL2, aL3);
            #pragma unroll
            for (int p = 0; p < 4; p++) {
                uint32_t bH0,bH1,bH2,bH3, bL0,bL1,bL2,bL3;
                uint32_t poff = (uint32_t)(p*16*80) + kb;
                ldsm4(base + boffH + poff, bH0, bH1, bH2, bH3);
                ldsm4(base + boffL + poff, bL0, bL1, bL2, bL3);
                int f0 = 2*p, f1 = 2*p + 1;
                mma16816(chh[f0],  aH0,aH1,aH2,aH3, bH0,bH1);
                mma16816(chh[f1],  aH0,aH1,aH2,aH3, bH2,bH3);
                mma16816(cmid[f0], aL0,aL1,aL2,aL3, bH0,bH1);
                mma16816(cmid[f1], aL0,aL1,aL2,aL3, bH2,bH3);
                mma16816(cmid[f0], aH0,aH1,aH2,aH3, bL0,bL1);
                mma16816(cmid[f1], aH0,aH1,aH2,aH3, bL2,bL3);
            }
        }
        __syncthreads();
        if (kc + 2 < NKC) issue(kc + 2, st);
        asm volatile("cp.async.commit_group;" ::: "memory");
    }

    int g = l >> 2, tig = l & 3;
    int row0 = m0 + wm*16 + g, row1 = row0 + 8;
    #pragma unroll
    for (int f = 0; f < 8; f++) {
        int n = n0 + f*8 + tig*2;
        float b0 = bih[n]   + bhh[n];
        float b1 = bih[n+1] + bhh[n+1];
        float2 v0, v1;
        v0.x = chh[f][0] + cmid[f][0]*LO_INV + b0;
        v0.y = chh[f][1] + cmid[f][1]*LO_INV + b1;
        v1.x = chh[f][2] + cmid[f][2]*LO_INV + b0;
        v1.y = chh[f][3] + cmid[f][3]*LO_INV + b1;
        *(float2*)&g_gates[(size_t)row0*GATES_ + n] = v0;
        *(float2*)&g_gates[(size_t)row1*GATES_ + n] = v1;
    }
}

// ---------------- fused LSTM pointwise + next-step gp ------------------------
// One CTA per sample, 512 threads (thread = hidden unit).
__global__ __launch_bounds__(512) void lstm_kernel(const float* __restrict__ Wg,
                                                   const float* __restrict__ bg,
                                                   float* out) {
    __shared__ float s_h[HID_];
    int b = blockIdx.x;
    int h = threadIdx.x;
    const float* gr = g_gates + (size_t)b * GATES_;
    float xi = gr[h], xf = gr[HID_ + h], xg = gr[2*HID_ + h], xo = gr[3*HID_ + h];
    float si = 1.f / (1.f + expf(-xi));
    float sf = 1.f / (1.f + expf(-xf));
    float so = 1.f / (1.f + expf(-xo));
    int idx = b*HID_ + h;
    float c = sf * g_C[idx] + si * tanhf(xg);
    float hh = so * tanhf(c);
    g_C[idx] = c; g_H[idx] = hh;
    __half hi, lo; split2(hh, hi, lo);
    g_Ahi[(size_t)b*KTOT_ + XDIM_ + h] = hi;
    g_Alo[(size_t)b*KTOT_ + XDIM_ + h] = lo;
    if (out) out[idx] = hh;
    s_h[h] = hh;
    __syncthreads();
    // gp for the NEXT step: 3 warps compute tanh(h . Wg_w + bg_w)
    int wid = h >> 5, lane = h & 31;
    if (wid < 3) {
        const float* wr = Wg + wid*HID_;
        float s = 0.f;
        #pragma unroll 4
        for (int k = lane; k < HID_; k += 32) s += s_h[k]*wr[k];
        #pragma unroll
        for (int o = 16; o; o >>= 1) s += __shfl_xor_sync(0xffffffffu, s, o);
        if (lane == 0) g_GP[b*3 + wid] = tanhf(s + bg[wid]);
    }
}

// ---------------- launcher ----------------------------------------------------
extern "C" void kernel_launch(void* const* d_in, const int* in_sizes, int n_in,
                              void* d_out, int out_size) {
    const float* imgs = (const float*)d_in[0];
    const float* Wih  = (const float*)d_in[1];
    const float* Whh  = (const float*)d_in[2];
    const float* bih  = (const float*)d_in[3];
    const float* bhh  = (const float*)d_in[4];
    const float* Wg   = (const float*)d_in[5];
    const float* bg   = (const float*)d_in[6];
    float* out = (float*)d_out;

    cudaFuncSetAttribute(glimpse_kernel, cudaFuncAttributeMaxDynamicSharedMemorySize,
                         SM_TOTAL);

    init_kernel<<<(B_*KTOT_ + 255)/256, 256>>>(bg);
    presplit_kernel<<<GATES_, 256>>>(Wih, Whh);
    presplit_img_kernel<<<B_*2, 256>>>(imgs);
    for (int t = 0; t < NSTEP_; t++) {
        glimpse_kernel<<<B_, 512, SM_TOTAL>>>(t & 1);
        gates_kernel<<<dim3(GATES_/64, B_/64), 128>>>(bih, bhh);
        lstm_kernel<<<B_, 512>>>(Wg, bg, t == NSTEP_-1 ? out : nullptr);
    }
}

// round 15
// speedup vs baseline: 1.0075x; 1.0075x over previous
#include <cuda_runtime.h>
#include <cuda_fp16.h>
#include <cstdint>
#include <cstddef>

#define B_      256
#define IMG_    256
#define G_      64
#define HID_    512
#define NSTEP_  16
#define GATES_  (4*HID_)     // 2048
#define XDIM_   (G_*G_)      // 4096
#define KTOT_   (XDIM_+HID_) // 4608
#define PI_     3.14159265358979f

// ---------------- scratch (static device globals; no allocation) -------------
__device__ float g_H[B_*HID_];
__device__ float g_C[B_*HID_];
__device__ float g_GP[B_*3];
__device__ float g_gates[B_*GATES_];
// split operands for the tensor-core gates GEMM
__device__ __half g_Ahi[B_*KTOT_];      // rows b, cols [X | H]
__device__ __half g_Alo[B_*KTOT_];
__device__ __half g_Whi[GATES_*KTOT_];  // rows n, cols [Wih | Whh]
__device__ __half g_Wlo[GATES_*KTOT_];
// split images (loop-invariant; split once per launch)
__device__ __half g_Ihi[B_*2*IMG_*IMG_];
__device__ __half g_Ilo[B_*2*IMG_*IMG_];

#define LO_SCALE 2048.0f
#define LO_INV   4.8828125e-4f

__device__ __forceinline__ void split2(float v, __half& hi, __half& lo) {
    hi = __float2half_rn(v);
    lo = __float2half_rn((v - __half2float(hi)) * LO_SCALE);
}

__device__ __forceinline__ void cp16(uint32_t dst, const void* src) {
    asm volatile("cp.async.cg.shared.global [%0], [%1], 16;" :: "r"(dst), "l"(src));
}
__device__ __forceinline__ void ldsm4(uint32_t addr, uint32_t& r0, uint32_t& r1,
                                      uint32_t& r2, uint32_t& r3) {
    asm volatile("ldmatrix.sync.aligned.m8n8.x4.shared.b16 {%0,%1,%2,%3}, [%4];"
                 : "=r"(r0), "=r"(r1), "=r"(r2), "=r"(r3) : "r"(addr));
}
__device__ __forceinline__ void mma16816(float* c, uint32_t a0, uint32_t a1,
                                         uint32_t a2, uint32_t a3,
                                         uint32_t b0, uint32_t b1) {
    asm volatile("mma.sync.aligned.m16n8k16.row.col.f32.f16.f16.f32 "
                 "{%0,%1,%2,%3}, {%4,%5,%6,%7}, {%8,%9}, {%0,%1,%2,%3};"
                 : "+f"(c[0]), "+f"(c[1]), "+f"(c[2]), "+f"(c[3])
                 : "r"(a0), "r"(a1), "r"(a2), "r"(a3), "r"(b0), "r"(b1));
}

// ---------------- init: zero H, C, A; seed GP for step 0 (H=0) ---------------
__global__ void init_kernel(const float* __restrict__ bg) {
    int i = blockIdx.x * blockDim.x + threadIdx.x;
    if (i < B_*HID_) { g_H[i] = 0.f; g_C[i] = 0.f; }
    if (i < B_*KTOT_) {
        g_Ahi[i] = __float2half(0.f);
        g_Alo[i] = __float2half(0.f);
    }
    if (i < B_*3) g_GP[i] = tanhf(bg[i % 3]);
}

// ---------------- pre-split W (once per launch) -------------------------------
__global__ void presplit_kernel(const float* __restrict__ Wih,
                                const float* __restrict__ Whh) {
    int n = blockIdx.x;
    for (int k = threadIdx.x; k < KTOT_; k += 256) {
        float w = (k < XDIM_) ? Wih[(size_t)n*XDIM_ + k]
                              : Whh[(size_t)n*HID_ + k - XDIM_];
        __half hi, lo; split2(w, hi, lo);
        g_Whi[(size_t)n*KTOT_ + k] = hi;
        g_Wlo[(size_t)n*KTOT_ + k] = lo;
    }
}

// ---------------- pre-split images (once per launch) --------------------------
__global__ void presplit_img_kernel(const float* __restrict__ imgs) {
    size_t base = (size_t)blockIdx.x * (IMG_*IMG_);
    for (int k = threadIdx.x; k < IMG_*IMG_; k += 256) {
        float v = imgs[base + k];
        __half hi, lo; split2(v, hi, lo);
        g_Ihi[base + k] = hi;
        g_Ilo[base + k] = lo;
    }
}

// ---------------- tensor-core glimpse: filterbank + 2 HMMA GEMMs -------------
#define SM_FW_HI  0
#define SM_FW_LO  33792
#define SM_IMG    67584
#define SM_T_HI   67584
#define SM_T_LO   101376
#define SM_RED    149504
#define SM_RW     151552
#define SM_RH     151808
#define SM_TOTAL  152064

extern __shared__ char gl_smem[];
__global__ __launch_bounds__(512, 1) void glimpse_kernel(int ch) {
    uint32_t sb = (uint32_t)__cvta_generic_to_shared(gl_smem);
    float* s_red = (float*)(gl_smem + SM_RED);
    float* s_rw  = (float*)(gl_smem + SM_RW);
    float* s_rh  = (float*)(gl_smem + SM_RH);

    int b = blockIdx.x;
    int t = threadIdx.x;
    int l = t & 31, wid = t >> 5;
    int rA = (l & 7) + 8*((l >> 3) & 1);
    int cA = l >> 4;
    int rB = (l & 7) + 8*(l >> 4);
    int cB = (l >> 3) & 1;
    int g  = l >> 2, tig = l & 3;

    size_t ibase = ((size_t)b*2 + ch) * (IMG_*IMG_);

    auto issue = [&](int cc) {
        int st = cc & 1;
        #pragma unroll
        for (int j = 0; j < 2; j++) {
            int uid = t + 512*j;
            int row = uid >> 2, u = uid & 3;
            size_t goff = ibase + (size_t)row*IMG_ + cc*32 + u*8;
            uint32_t doff = sb + SM_IMG + st*40960 + row*80 + u*16;
            cp16(doff, g_Ihi + goff);
            cp16(doff + 20480, g_Ilo + goff);
        }
    };
    issue(0); asm volatile("cp.async.commit_group;" ::: "memory");
    issue(1); asm volatile("cp.async.commit_group;" ::: "memory");

    float d   = g_GP[b*3 + 2];
    float ch0 = g_GP[b*3 + 0];
    float cw  = g_GP[b*3 + 1];
    float ad      = fabsf(d);
    float delta   = 4.f * (1.f - ad);
    float gamma   = expf(1.f - 2.f*ad);
    float inv_g   = 1.f / gamma;
    float eps_adj = 1e-4f * PI_ * gamma;
    float center_h = 127.5f * (ch0 + 1.f);
    float center_w = 127.5f * (cw  + 1.f);

    {
        int j = t & 63, wg = t >> 6;
        float mu = center_w + delta * ((float)j - 31.5f);
        __half* fh = (__half*)(gl_smem + SM_FW_HI) + j*264;
        __half* fl = (__half*)(gl_smem + SM_FW_LO) + j*264;
        float s = 0.f;
        #pragma unroll 8
        for (int w = wg*32; w < wg*32 + 32; w++) {
            float u = ((float)w - mu) * inv_g;
            float v = 1.f / (1.f + u*u);
            s += v;
            __half hi, lo; split2(v, hi, lo);
            fh[w] = hi; fl[w] = lo;
        }
        s_red[t] = s;
    }
    __syncthreads();
    if (t < 64) {
        float s = 0.f;
        #pragma unroll
        for (int p = 0; p < 8; p++) s += s_red[t + 64*p];
        s_rw[t] = 1.f / (s + eps_adj);
    }

    int mt = wid;
    float chh[8][4], cmid[8][4];
    #pragma unroll
    for (int f = 0; f < 8; f++)
        #pragma unroll
        for (int q = 0; q < 4; q++) { chh[f][q] = 0.f; cmid[f][q] = 0.f; }

    for (int c = 0; c < 8; c++) {
        asm volatile("cp.async.wait_group 1;" ::: "memory");
        __syncthreads();
        uint32_t ahB = sb + SM_IMG + (c & 1)*40960 + (mt*16 + rA)*80 + cA*16;
        uint32_t alB = ahB + 20480;
        #pragma unroll
        for (int ks = 0; ks < 2; ks++) {
            uint32_t kb = ks*32;
            uint32_t aH0,aH1,aH2,aH3, aL0,aL1,aL2,aL3;
            ldsm4(ahB + kb, aH0, aH1, aH2, aH3);
            ldsm4(alB + kb, aL0, aL1, aL2, aL3);
            #pragma unroll
            for (int p = 0; p < 4; p++) {
                uint32_t bh = sb + SM_FW_HI + (uint32_t)((p*16 + rB)*528) + c*64 + cB*16 + kb;
                uint32_t bH0,bH1,bH2,bH3, bL0,bL1,bL2,bL3;
                ldsm4(bh, bH0, bH1, bH2, bH3);
                ldsm4(bh + 33792, bL0, bL1, bL2, bL3);
                int f0 = 2*p, f1 = 2*p + 1;
                mma16816(chh[f0],  aH0,aH1,aH2,aH3, bH0,bH1);
                mma16816(chh[f1],  aH0,aH1,aH2,aH3, bH2,bH3);
                mma16816(cmid[f0], aL0,aL1,aL2,aL3, bH0,bH1);
                mma16816(cmid[f1], aL0,aL1,aL2,aL3, bH2,bH3);
                mma16816(cmid[f0], aH0,aH1,aH2,aH3, bL0,bL1);
                mma16816(cmid[f1], aH0,aH1,aH2,aH3, bL2,bL3);
            }
        }
        __syncthreads();
        if (c + 2 < 8) issue(c + 2);
        asm volatile("cp.async.commit_group;" ::: "memory");
    }
    __syncthreads();

    {
        __half* th = (__half*)(gl_smem + SM_T_HI);
        __half* tl = (__half*)(gl_smem + SM_T_LO);
        #pragma unroll
        for (int f = 0; f < 8; f++) {
            #pragma unroll
            for (int q = 0; q < 4; q++) {
                int j = f*8 + tig*2 + (q & 1);
                int r = mt*16 + g + 8*(q >> 1);
                float val = (chh[f][q] + cmid[f][q]*LO_INV) * s_rw[j];
                __half hi, lo; split2(val, hi, lo);
                th[j*264 + r] = hi;
                tl[j*264 + r] = lo;
            }
        }
    }

    {
        int i = t & 63, rg = t >> 6;
        float mu = center_h + delta * ((float)i - 31.5f);
        __half* fh = (__half*)(gl_smem + SM_FW_HI) + i*264;
        __half* fl = (__half*)(gl_smem + SM_FW_LO) + i*264;
        float s = 0.f;
        #pragma unroll 8
        for (int r = rg*32; r < rg*32 + 32; r++) {
            float u = ((float)r - mu) * inv_g;
            float v = 1.f / (1.f + u*u);
            s += v;
            __half hi, lo; split2(v, hi, lo);
            fh[r] = hi; fl[r] = lo;
        }
        s_red[t] = s;
    }
    __syncthreads();
    if (t < 64) {
        float s = 0.f;
        #pragma unroll
        for (int p = 0; p < 8; p++) s += s_red[t + 64*p];
        s_rh[t] = 1.f / (s + eps_adj);
    }
    __syncthreads();

    int mt2 = wid & 3, np = wid >> 2;
    float c2h[2][4], c2m[2][4];
    #pragma unroll
    for (int f = 0; f < 2; f++)
        #pragma unroll
        for (int q = 0; q < 4; q++) { c2h[f][q] = 0.f; c2m[f][q] = 0.f; }

    #pragma unroll 2
    for (int ks2 = 0; ks2 < 16; ks2++) {
        uint32_t kb = (uint32_t)ks2*32;
        uint32_t ah = sb + SM_FW_HI + (uint32_t)((mt2*16 + rA)*528) + kb + cA*16;
        uint32_t bh = sb + SM_T_HI  + (uint32_t)((np*16 + rB)*528) + kb + cB*16;
        uint32_t aH0,aH1,aH2,aH3, aL0,aL1,aL2,aL3;
        uint32_t bH0,bH1,bH2,bH3, bL0,bL1,bL2,bL3;
        ldsm4(ah, aH0, aH1, aH2, aH3);
        ldsm4(ah + 33792, aL0, aL1, aL2, aL3);
        ldsm4(bh, bH0, bH1, bH2, bH3);
        ldsm4(bh + 33792, bL0, bL1, bL2, bL3);
        mma16816(c2h[0], aH0,aH1,aH2,aH3, bH0,bH1);
        mma16816(c2h[1], aH0,aH1,aH2,aH3, bH2,bH3);
        mma16816(c2m[0], aL0,aL1,aL2,aL3, bH0,bH1);
        mma16816(c2m[1], aL0,aL1,aL2,aL3, bH2,bH3);
        mma16816(c2m[0], aH0,aH1,aH2,aH3, bL0,bL1);
        mma16816(c2m[1], aH0,aH1,aH2,aH3, bL2,bL3);
    }

    {
        __half* ahi = g_Ahi + (size_t)b * KTOT_;
        __half* alo = g_Alo + (size_t)b * KTOT_;
        #pragma unroll
        for (int f = 0; f < 2; f++) {
            #pragma unroll
            for (int q = 0; q < 4; q++) {
                int i = mt2*16 + g + 8*(q >> 1);
                int j = np*16 + f*8 + tig*2 + (q & 1);
                float val = (c2h[f][q] + c2m[f][q]*LO_INV) * s_rh[i];
                __half hi, lo; split2(val, hi, lo);
                ahi[i*64 + j] = hi;
                alo[i*64 + j] = lo;
            }
        }
    }
}

// ---------------- gates GEMM: 64m x 64n tile, 128 thr, 2-stage cp.async ------
#define AHOFF   0
#define ALOFF   5120
#define BHOFF   10240
#define BLOFF   15360
#define SSTAGE  20480
#define NKC     144     // 4608 / 32

__global__ __launch_bounds__(128) void gates_kernel(
        const float* __restrict__ bih, const float* __restrict__ bhh) {
    __shared__ __align__(128) unsigned char gsm[2*SSTAGE];
    uint32_t sb = (uint32_t)__cvta_generic_to_shared(gsm);

    int t = threadIdx.x;
    int l = t & 31, wm = t >> 5;                   // 4 warps: m-subtile
    int m0 = blockIdx.y * 64, n0 = blockIdx.x * 64;

    int rA = (l & 7) + 8*((l >> 3) & 1) + wm*16;
    int cA = l >> 4;
    uint32_t aoffH = AHOFF + rA*80 + cA*16;
    uint32_t aoffL = ALOFF + rA*80 + cA*16;
    int rB = (l & 7) + 8*(l >> 4);
    int cB = (l >> 3) & 1;
    uint32_t boffH = BHOFF + rB*80 + cB*16;
    uint32_t boffL = BLOFF + rB*80 + cB*16;

    float chh[8][4], cmid[8][4];
    #pragma unroll
    for (int f = 0; f < 8; f++)
        #pragma unroll
        for (int q = 0; q < 4; q++) { chh[f][q] = 0.f; cmid[f][q] = 0.f; }

    auto issue = [&](int kc, int st) {
        uint32_t base = sb + st*SSTAGE;
        int k0 = kc * 32;
        #pragma unroll
        for (int j = 0; j < 2; j++) {              // A: 256 16B units (64 rows)
            int uid = t + 128*j;
            int row = uid >> 2, u = uid & 3;
            size_t gidx = (size_t)(m0 + row)*KTOT_ + k0 + u*8;
            uint32_t doff = row*80 + u*16;
            cp16(base + AHOFF + doff, g_Ahi + gidx);
            cp16(base + ALOFF + doff, g_Alo + gidx);
        }
        #pragma unroll
        for (int j = 0; j < 2; j++) {              // B: 256 16B units (64 rows)
            int uid = t + 128*j;
            int row = uid >> 2, u = uid & 3;
            size_t gidx = (size_t)(n0 + row)*KTOT_ + k0 + u*8;
            uint32_t doff = row*80 + u*16;
            cp16(base + BHOFF + doff, g_Whi + gidx);
            cp16(base + BLOFF + doff, g_Wlo + gidx);
        }
    };

    issue(0, 0); asm volatile("cp.async.commit_group;" ::: "memory");
    issue(1, 1); asm volatile("cp.async.commit_group;" ::: "memory");

    for (int kc = 0; kc < NKC; kc++) {
        int st = kc & 1;
        asm volatile("cp.async.wait_group 1;" ::: "memory");
        __syncthreads();
        uint32_t base = sb + st*SSTAGE;
        #pragma unroll
        for (int ks = 0; ks < 2; ks++) {
            uint32_t kb = ks*32;
            uint32_t aH0,aH1,aH2,aH3, aL0,aL1,aL2,aL3;
            ldsm4(base + aoffH + kb, aH0, aH1, aH2, aH3);
            ldsm4(base + aoffL + kb, aL0, aL1, aL2, aL3);
            #pragma unroll
            for (int p = 0; p < 4; p++) {
                uint32_t bH0,bH1,bH2,bH3, bL0,bL1,bL2,bL3;
                uint32_t poff = (uint32_t)(p*16*80) + kb;
                ldsm4(base + boffH + poff, bH0, bH1, bH2, bH3);
                ldsm4(base + boffL + poff, bL0, bL1, bL2, bL3);
                int f0 = 2*p, f1 = 2*p + 1;
                mma16816(chh[f0],  aH0,aH1,aH2,aH3, bH0,bH1);
                mma16816(chh[f1],  aH0,aH1,aH2,aH3, bH2,bH3);
                mma16816(cmid[f0], aL0,aL1,aL2,aL3, bH0,bH1);
                mma16816(cmid[f1], aL0,aL1,aL2,aL3, bH2,bH3);
                mma16816(cmid[f0], aH0,aH1,aH2,aH3, bL0,bL1);
                mma16816(cmid[f1], aH0,aH1,aH2,aH3, bL2,bL3);
            }
        }
        __syncthreads();
        if (kc + 2 < NKC) issue(kc + 2, st);
        asm volatile("cp.async.commit_group;" ::: "memory");
    }

    int g = l >> 2, tig = l & 3;
    int row0 = m0 + wm*16 + g, row1 = row0 + 8;
    #pragma unroll
    for (int f = 0; f < 8; f++) {
        int n = n0 + f*8 + tig*2;
        float b0 = bih[n]   + bhh[n];
        float b1 = bih[n+1] + bhh[n+1];
        float2 v0, v1;
        v0.x = chh[f][0] + cmid[f][0]*LO_INV + b0;
        v0.y = chh[f][1] + cmid[f][1]*LO_INV + b1;
        v1.x = chh[f][2] + cmid[f][2]*LO_INV + b0;
        v1.y = chh[f][3] + cmid[f][3]*LO_INV + b1;
        *(float2*)&g_gates[(size_t)row0*GATES_ + n] = v0;
        *(float2*)&g_gates[(size_t)row1*GATES_ + n] = v1;
    }
}

// ---------------- fused LSTM pointwise + next-step gp ------------------------
// One CTA per sample, 512 threads (thread = hidden unit).
__global__ __launch_bounds__(512) void lstm_kernel(const float* __restrict__ Wg,
                                                   const float* __restrict__ bg,
                                                   float* out) {
    __shared__ float s_h[HID_];
    int b = blockIdx.x;
    int h = threadIdx.x;
    const float* gr = g_gates + (size_t)b * GATES_;
    float xi = gr[h], xf = gr[HID_ + h], xg = gr[2*HID_ + h], xo = gr[3*HID_ + h];
    float si = 1.f / (1.f + expf(-xi));
    float sf = 1.f / (1.f + expf(-xf));
    float so = 1.f / (1.f + expf(-xo));
    int idx = b*HID_ + h;
    float c = sf * g_C[idx] + si * tanhf(xg);
    float hh = so * tanhf(c);
    g_C[idx] = c; g_H[idx] = hh;
    __half hi, lo; split2(hh, hi, lo);
    g_Ahi[(size_t)b*KTOT_ + XDIM_ + h] = hi;
    g_Alo[(size_t)b*KTOT_ + XDIM_ + h] = lo;
    if (out) out[idx] = hh;
    s_h[h] = hh;
    __syncthreads();
    // gp for the NEXT step: 3 warps compute tanh(h . Wg_w + bg_w)
    int wid = h >> 5, lane = h & 31;
    if (wid < 3) {
        const float* wr = Wg + wid*HID_;
        float s = 0.f;
        #pragma unroll 4
        for (int k = lane; k < HID_; k += 32) s += s_h[k]*wr[k];
        #pragma unroll
        for (int o = 16; o; o >>= 1) s += __shfl_xor_sync(0xffffffffu, s, o);
        if (lane == 0) g_GP[b*3 + wid] = tanhf(s + bg[wid]);
    }
}

// ---------------- launcher ----------------------------------------------------
extern "C" void kernel_launch(void* const* d_in, const int* in_sizes, int n_in,
                              void* d_out, int out_size) {
    const float* imgs = (const float*)d_in[0];
    const float* Wih  = (const float*)d_in[1];
    const float* Whh  = (const float*)d_in[2];
    const float* bih  = (const float*)d_in[3];
    const float* bhh  = (const float*)d_in[4];
    const float* Wg   = (const float*)d_in[5];
    const float* bg   = (const float*)d_in[6];
    float* out = (float*)d_out;

    cudaFuncSetAttribute(glimpse_kernel, cudaFuncAttributeMaxDynamicSharedMemorySize,
                         SM_TOTAL);

    init_kernel<<<(B_*KTOT_ + 255)/256, 256>>>(bg);
    presplit_kernel<<<GATES_, 256>>>(Wih, Whh);
    presplit_img_kernel<<<B_*2, 256>>>(imgs);
    for (int t = 0; t < NSTEP_; t++) {
        glimpse_kernel<<<B_, 512, SM_TOTAL>>>(t & 1);
        gates_kernel<<<dim3(GATES_/64, B_/64), 128>>>(bih, bhh);
        lstm_kernel<<<B_, 512>>>(Wg, bg, t == NSTEP_-1 ? out : nullptr);
    }
}